// round 10
// baseline (speedup 1.0000x reference)
#include <cuda_runtime.h>
#include <cuda_fp16.h>
#include <cstdint>
#include <math.h>

#define TPB 256
#define PCH 128                 // points per kp chunk (2 sub-tiles of 64)

static __device__ __forceinline__ uint32_t s2u(const void* p) {
    uint32_t a;
    asm("{ .reg .u64 t; cvta.to.shared.u64 t, %1; cvt.u32.u64 %0, t; }" : "=r"(a) : "l"(p));
    return a;
}
static __device__ __forceinline__ float fast_exp2(float x) {
    float y; asm("ex2.approx.ftz.f32 %0, %1;" : "=f"(y) : "f"(x)); return y;
}
static __device__ __forceinline__ uint32_t pack_h2(float lo, float hi) {
    uint32_t u;
    asm("cvt.rn.f16x2.f32 %0, %1, %2;" : "=r"(u) : "f"(hi), "f"(lo));  // d.lo = %2
    return u;
}
static __device__ __forceinline__ uint32_t sw128(uint32_t off) {
    return off ^ ((off >> 3) & 0x70);
}
static __device__ __forceinline__ void ldsm_x4(uint32_t addr, uint32_t& r0, uint32_t& r1,
                                               uint32_t& r2, uint32_t& r3) {
    asm volatile("ldmatrix.sync.aligned.m8n8.x4.shared.b16 {%0,%1,%2,%3}, [%4];"
                 : "=r"(r0), "=r"(r1), "=r"(r2), "=r"(r3) : "r"(addr));
}
static __device__ __forceinline__ void mma16816(float* c, uint32_t a0, uint32_t a1,
                                                uint32_t a2, uint32_t a3,
                                                uint32_t b0, uint32_t b1) {
    asm volatile(
        "mma.sync.aligned.m16n8k16.row.col.f32.f16.f16.f32 "
        "{%0,%1,%2,%3}, {%4,%5,%6,%7}, {%8,%9}, {%0,%1,%2,%3};"
        : "+f"(c[0]), "+f"(c[1]), "+f"(c[2]), "+f"(c[3])
        : "r"(a0), "r"(a1), "r"(a2), "r"(a3), "r"(b0), "r"(b1));
}
static __device__ __forceinline__ void red_v2(float* p, float x, float y) {
    asm volatile("red.global.add.v2.f32 [%0], {%1, %2};"
                 :: "l"(p), "f"(x), "f"(y) : "memory");
}

// dynamic smem: A[2][8KB] (64h x 64p each) | B[2][16KB] (128w x 64p) | bx,by,vc[128]
#define OFF_A    0
#define OFF_B    16384
#define OFF_BX   49152
#define OFF_BY   49664
#define OFF_VC   50176
#define SMEM_SZ  50688

// CTA = (kp chunk of 128 points, h-half, channel c, batch n).
// out[64h x 128w] += sum_p ey[h,p] * (ex[w,p] * v[p,c])  via red.global.v2 (no scratch)
__global__ void __launch_bounds__(TPB, 2)
splat2d_hmma_kernel(const float* __restrict__ coords,   // [N,P,2]
                    const float* __restrict__ values,   // [N,P,3]
                    const float* __restrict__ sigma,    // [N,1]
                    float* __restrict__ out,            // [N,3,128,128]
                    int P) {
    extern __shared__ __align__(1024) char smem[];
    float* bx = (float*)(smem + OFF_BX);
    float* by = (float*)(smem + OFF_BY);
    float* vc = (float*)(smem + OFF_VC);

    const int tid = threadIdx.x;
    const int kp  = blockIdx.x >> 1;
    const int hh  = blockIdx.x & 1;         // h-half: rows [hh*64, hh*64+64)
    const int c   = blockIdx.y;
    const int n   = blockIdx.z;
    const int p0  = kp * PCH;
    const int hbase = hh * 64;

    const float sg = sigma[n];
    const float a_ = sqrtf(0.72134752044448169f) / sg;   // sqrt(log2(e)/2)/sigma

    const float2* cb2 = (const float2*)coords + (size_t)n * P;
    const float*  vb  = values + (size_t)n * P * 3;

    if (tid < PCH) {
        const float2 cd = cb2[p0 + tid];
        bx[tid] = a_ * cd.x;
        by[tid] = a_ * cd.y;
        vc[tid] = vb[(p0 + tid) * 3 + c];
    }
    __syncthreads();

    const uint32_t Abase = s2u(smem + OFF_A);
    const uint32_t Bbase = s2u(smem + OFF_B);

    // ---- A tiles: ey[h][p], 64h x 128p as 2 sub-tiles of 64h x 64p, SW128 ----
    // h lane-consecutive, pg warp-uniform -> all point-table LDS are broadcasts
    for (int task = tid; task < 1024; task += TPB) {
        const int h   = task & 63;
        const int pg  = task >> 6;          // 0..15
        const int ts  = pg >> 3;
        const int pgl = pg & 7;
        const float ah = a_ * (float)(hbase + h);
        float e[8];
        #pragma unroll
        for (int i = 0; i < 8; ++i) {
            const float d = ah - by[pg * 8 + i];   // broadcast
            e[i] = fast_exp2(-d * d);
        }
        const uint32_t q0 = pack_h2(e[0], e[1]);
        const uint32_t q1 = pack_h2(e[2], e[3]);
        const uint32_t q2 = pack_h2(e[4], e[5]);
        const uint32_t q3 = pack_h2(e[6], e[7]);
        asm volatile("st.shared.v4.b32 [%0], {%1,%2,%3,%4};"
                     :: "r"(Abase + ts * 8192 + sw128((uint32_t)(h * 128 + pgl * 16))),
                        "r"(q0), "r"(q1), "r"(q2), "r"(q3));
    }
    // ---- B tiles: (ex * vc)[w][p], 128w x 128p as 2 sub-tiles of 128w x 64p ----
    for (int task = tid; task < 2048; task += TPB) {
        const int w   = task & 127;
        const int pg  = task >> 7;          // 0..15, warp-uniform
        const int ts  = pg >> 3;
        const int pgl = pg & 7;
        const float aw = a_ * (float)w;
        float m[8];
        #pragma unroll
        for (int i = 0; i < 8; ++i) {
            const float d = aw - bx[pg * 8 + i];   // broadcast
            m[i] = fast_exp2(-d * d) * vc[pg * 8 + i];
        }
        const uint32_t q0 = pack_h2(m[0], m[1]);
        const uint32_t q1 = pack_h2(m[2], m[3]);
        const uint32_t q2 = pack_h2(m[4], m[5]);
        const uint32_t q3 = pack_h2(m[6], m[7]);
        asm volatile("st.shared.v4.b32 [%0], {%1,%2,%3,%4};"
                     :: "r"(Bbase + ts * 16384 + sw128((uint32_t)(w * 128 + pgl * 16))),
                        "r"(q0), "r"(q1), "r"(q2), "r"(q3));
    }
    __syncthreads();

    // ---- consumer: 8 warps, warp tile 16h x 64w, 2 sub-tiles x 4 K-steps ----
    const int wid  = tid >> 5;
    const int lane = tid & 31;
    const int h0   = (wid & 3) * 16;
    const int w0   = (wid >> 2) * 64;

    float acc[8][4];
    #pragma unroll
    for (int nb = 0; nb < 8; ++nb)
        #pragma unroll
        for (int j = 0; j < 4; ++j) acc[nb][j] = 0.f;

    const int a_row = lane & 15;
    const int a_kb  = (lane >> 4) << 4;
    const int b_row = (((lane >> 4) & 1) << 3) + (lane & 7);
    const int b_kb  = ((lane >> 3) & 1) << 4;

    #pragma unroll
    for (int ts = 0; ts < 2; ++ts) {
        const uint32_t Asub = Abase + ts * 8192;
        const uint32_t Bsub = Bbase + ts * 16384;
        #pragma unroll
        for (int ks = 0; ks < 4; ++ks) {
            const uint32_t kbyte = ks * 32;   // 16 f16 per K-step

            uint32_t a0, a1, a2, a3;
            ldsm_x4(Asub + sw128((uint32_t)((h0 + a_row) * 128) + kbyte + a_kb),
                    a0, a1, a2, a3);
            uint32_t b[4][4];
            #pragma unroll
            for (int nb16 = 0; nb16 < 4; ++nb16) {
                const uint32_t row = (uint32_t)(w0 + nb16 * 16 + b_row);
                ldsm_x4(Bsub + sw128(row * 128 + kbyte + b_kb),
                        b[nb16][0], b[nb16][1], b[nb16][2], b[nb16][3]);
            }
            #pragma unroll
            for (int nb = 0; nb < 8; ++nb)
                mma16816(acc[nb], a0, a1, a2, a3,
                         b[nb >> 1][(nb & 1) ? 2 : 0], b[nb >> 1][(nb & 1) ? 3 : 1]);
        }
    }

    // ---- epilogue: vectorized global reductions straight into out ----
    const int r  = lane >> 2;
    const int c2 = (lane & 3) * 2;
    float* ob = out + (((size_t)n * 3 + c) << 14);
    #pragma unroll
    for (int nb = 0; nb < 8; ++nb) {
        const int hhg = hbase + h0 + r;
        const int ww  = w0 + nb * 8 + c2;
        float* p = ob + hhg * 128 + ww;
        red_v2(p,           acc[nb][0], acc[nb][1]);
        red_v2(p + 8 * 128, acc[nb][2], acc[nb][3]);
    }
}

extern "C" void kernel_launch(void* const* d_in, const int* in_sizes, int n_in,
                              void* d_out, int out_size) {
    const float* coords = (const float*)d_in[0];   // [N,P,2]
    const float* values = (const float*)d_in[1];   // [N,P,C]
    const float* sigma  = (const float*)d_in[2];   // [N,1]

    const int N = in_sizes[2];
    const int P = in_sizes[0] / (2 * N);           // 1024
    const int kch = P / PCH;                       // 8

    cudaFuncSetAttribute(splat2d_hmma_kernel,
                         cudaFuncAttributeMaxDynamicSharedMemorySize, SMEM_SZ);

    cudaMemsetAsync(d_out, 0, (size_t)out_size * sizeof(float), 0);

    dim3 grid(kch * 2, 3, N);                      // 16 x 3 x 4 = 192 CTAs
    splat2d_hmma_kernel<<<grid, TPB, SMEM_SZ>>>(coords, values, sigma, (float*)d_out, P);
}